// round 6
// baseline (speedup 1.0000x reference)
#include <cuda_runtime.h>
#include <cuda_bf16.h>
#include <cuda_fp8.h>
#include <math.h>
#include <cstdint>

#define Bq   128
#define Tq   256
#define Eq   512
#define Hq   1024
#define TOPq 128
#define Fq   512
#define Oq   10
#define G4   4096
#define NH   8
#define BH   (Bq * Hq)

typedef unsigned long long u64;
typedef unsigned int u32;
typedef unsigned char u8;

// ---------------- device scratch ----------------
__device__ float g_xg[(size_t)Bq * Tq * G4];
__device__ float g_tb[Bq * G4];
__device__ float g_hbuf[Bq * Hq];
__device__ __nv_bfloat16 g_hhi[2 * BH];            // bf16(h)
__device__ u8 g_h8a[2 * BH];                       // e4m3(h)
__device__ u8 g_h8lo[2 * BH];                      // e4m3((h - bf16(h)) * 512)
__device__ __nv_bfloat16 g_whi[(size_t)G4 * Hq];   // bf16(w)
__device__ u8 g_w8hi[(size_t)G4 * Hq];             // e4m3(w * 256)
__device__ u8 g_w8lo[(size_t)G4 * Hq];             // e4m3((w - bf16(w)) * 131072)
__device__ __nv_bfloat16 g_xeb[(size_t)Bq * Tq * Eq];
__device__ __nv_bfloat16 g_wihb[(size_t)G4 * Eq];
__device__ float g_h1[Bq * Fq];
__device__ float g_s[Fq];
__device__ float g_t[Fq];
__device__ unsigned int g_bar;

#define CROSS_INV (1.0f / 131072.0f)

// ---------------- helpers ----------------
__device__ __forceinline__ float sigmoidf(float x) { return 1.0f / (1.0f + expf(-x)); }

__device__ __forceinline__ u32 smem_u32(const void* p) {
    u32 a; asm("{ .reg .u64 t; cvta.to.shared.u64 t, %1; cvt.u32.u64 %0, t; }" : "=r"(a) : "l"(p));
    return a;
}
__device__ __forceinline__ void ldm4(u32 &r0, u32 &r1, u32 &r2, u32 &r3, u32 addr) {
    asm volatile("ldmatrix.sync.aligned.m8n8.x4.shared.b16 {%0,%1,%2,%3}, [%4];"
        : "=r"(r0), "=r"(r1), "=r"(r2), "=r"(r3) : "r"(addr));
}
__device__ __forceinline__ u32 lds32(u32 addr) {
    u32 v; asm volatile("ld.shared.b32 %0, [%1];" : "=r"(v) : "r"(addr)); return v;
}
__device__ __forceinline__ void mma16816(float* d, const u32* a, u32 b0, u32 b1) {
    asm volatile("mma.sync.aligned.m16n8k16.row.col.f32.bf16.bf16.f32 "
        "{%0,%1,%2,%3}, {%4,%5,%6,%7}, {%8,%9}, {%0,%1,%2,%3};"
        : "+f"(d[0]), "+f"(d[1]), "+f"(d[2]), "+f"(d[3])
        : "r"(a[0]), "r"(a[1]), "r"(a[2]), "r"(a[3]), "r"(b0), "r"(b1));
}
__device__ __forceinline__ void mma16832q(float* d, const u32* a, u32 b0, u32 b1) {
    asm volatile("mma.sync.aligned.m16n8k32.row.col.f32.e4m3.e4m3.f32 "
        "{%0,%1,%2,%3}, {%4,%5,%6,%7}, {%8,%9}, {%0,%1,%2,%3};"
        : "+f"(d[0]), "+f"(d[1]), "+f"(d[2]), "+f"(d[3])
        : "r"(a[0]), "r"(a[1]), "r"(a[2]), "r"(a[3]), "r"(b0), "r"(b1));
}
__device__ __forceinline__ void cpa16(u32 dst, const void* src) {
    asm volatile("cp.async.cg.shared.global [%0], [%1], 16;" :: "r"(dst), "l"(src));
}
#define CP_COMMIT() asm volatile("cp.async.commit_group;" ::: "memory")
#define CP_WAIT0()  asm volatile("cp.async.wait_group 0;" ::: "memory")

__device__ __forceinline__ u8 f2e4m3(float x) {
    return (u8)__nv_cvt_float_to_fp8(x, __NV_SATFINITE, __NV_E4M3);
}

// ---------------- init ----------------
__global__ void k_init() {
    int i = blockIdx.x * blockDim.x + threadIdx.x;
    if (i == 0) g_bar = 0u;
    if (i < BH) {
        g_hhi[i] = __float2bfloat16(0.f);
        g_h8a[i] = 0;
        g_h8lo[i] = 0;
    }
}

// ---------------- w_hh prep: bf16 hi + fp8 (scaled) ----------------
__global__ __launch_bounds__(256) void k_wsplit(const float* __restrict__ w) {
    size_t i = ((size_t)blockIdx.x * 256 + threadIdx.x) * 4;
    float4 v = *(const float4*)(w + i);
    float vv[4] = {v.x, v.y, v.z, v.w};
    __nv_bfloat16 hi[4];
    u32 p8hi = 0, p8lo = 0;
    #pragma unroll
    for (int j = 0; j < 4; j++) {
        hi[j] = __float2bfloat16(vv[j]);
        float lo = vv[j] - __bfloat162float(hi[j]);
        p8hi |= (u32)f2e4m3(vv[j] * 256.0f) << (j * 8);
        p8lo |= (u32)f2e4m3(lo * 131072.0f) << (j * 8);
    }
    *(uint2*)(g_whi + i) = *(uint2*)hi;
    *(u32*)(g_w8hi + i) = p8hi;
    *(u32*)(g_w8lo + i) = p8lo;
}

// ---------------- w_ih -> bf16 ----------------
__global__ __launch_bounds__(256) void k_wihb(const float* __restrict__ w) {
    size_t i = ((size_t)blockIdx.x * 256 + threadIdx.x) * 4;
    float4 v = *(const float4*)(w + i);
    __nv_bfloat16 b[4] = {__float2bfloat16(v.x), __float2bfloat16(v.y),
                          __float2bfloat16(v.z), __float2bfloat16(v.w)};
    *(uint2*)(g_wihb + i) = *(uint2*)b;
}

// ---------------- emb gather -> bf16 ----------------
__global__ __launch_bounds__(256) void k_xeb(const int* __restrict__ x,
                                             const float* __restrict__ emb) {
    size_t idx = (size_t)blockIdx.x * 256 + threadIdx.x;
    int m = (int)(idx >> 7);
    int e4 = ((int)idx & 127) * 4;
    int row = x[m];
    float4 v = *(const float4*)(emb + (size_t)row * Eq + e4);
    __nv_bfloat16 b[4] = {__float2bfloat16(v.x), __float2bfloat16(v.y),
                          __float2bfloat16(v.z), __float2bfloat16(v.w)};
    *(uint2*)(g_xeb + (size_t)m * Eq + e4) = *(uint2*)b;
}

// ---------------- topic bias ----------------
__global__ __launch_bounds__(256) void k_topic(const float* __restrict__ x_top,
                                               const float* __restrict__ w_th,
                                               const float* __restrict__ bias) {
    __shared__ float xt[TOPq];
    int b = blockIdx.x, tid = threadIdx.x;
    if (tid < TOPq) xt[tid] = x_top[b * TOPq + tid];
    __syncthreads();
    for (int g = tid; g < G4; g += 256) {
        const float4* wr = (const float4*)(w_th + (size_t)g * TOPq);
        float s = bias[g];
        #pragma unroll
        for (int k = 0; k < TOPq / 4; k++) {
            float4 w4 = wr[k];
            s += xt[4*k]*w4.x + xt[4*k+1]*w4.y + xt[4*k+2]*w4.z + xt[4*k+3]*w4.w;
        }
        g_tb[b * G4 + g] = s;
    }
}

// ---------------- xg GEMM (bf16 tensor, cp.async; unchanged) ----------------
#define XA_STRIDE 144
#define XA_HALF   18432
#define XB_BASE   36864
#define XB_HALF   9216
#define XG_SMEM   55296

__global__ __launch_bounds__(256) void k_xg_t() {
    extern __shared__ char dsm[];
    int tid = threadIdx.x, wid = tid >> 5, lane = tid & 31;
    int n0 = blockIdx.x * 64;
    int m0 = blockIdx.y * 128;

    int arow[4], ac[4];
    #pragma unroll
    for (int i = 0; i < 4; i++) { int u = tid + i * 256; arow[i] = u >> 3; ac[i] = u & 7; }
    int brow[2], bc[2];
    #pragma unroll
    for (int i = 0; i < 2; i++) { int u = tid + i * 256; brow[i] = u >> 3; bc[i] = u & 7; }

    u32 sb = smem_u32(dsm);
    int amrow = wid * 16 + (lane & 7) + ((lane >> 3) & 1) * 8;
    u32 aAddr = sb + amrow * XA_STRIDE + (lane >> 4) * 16;
    u32 bAddr = sb + XB_BASE + lane * XA_STRIDE;

    float acc[8][4];
    #pragma unroll
    for (int i = 0; i < 8; i++) { acc[i][0]=0.f; acc[i][1]=0.f; acc[i][2]=0.f; acc[i][3]=0.f; }

    const __nv_bfloat16* Ag = g_xeb + (size_t)m0 * Eq;
    const __nv_bfloat16* Bg = g_wihb + (size_t)n0 * Eq;

    {
        u32 aS = sb, bS = sb + XB_BASE;
        #pragma unroll
        for (int i = 0; i < 4; i++)
            cpa16(aS + arow[i] * XA_STRIDE + ac[i] * 16, Ag + (size_t)arow[i] * Eq + ac[i] * 8);
        #pragma unroll
        for (int i = 0; i < 2; i++)
            cpa16(bS + brow[i] * XA_STRIDE + bc[i] * 16, Bg + (size_t)brow[i] * Eq + bc[i] * 8);
        CP_COMMIT();
    }

    for (int c = 0; c < 8; c++) {
        int buf = c & 1;
        CP_WAIT0();
        __syncthreads();
        if (c < 7) {
            int k0 = (c + 1) * 64;
            u32 aS = sb + (buf ^ 1) * XA_HALF;
            u32 bS = sb + XB_BASE + (buf ^ 1) * XB_HALF;
            #pragma unroll
            for (int i = 0; i < 4; i++)
                cpa16(aS + arow[i] * XA_STRIDE + ac[i] * 16, Ag + (size_t)arow[i] * Eq + k0 + ac[i] * 8);
            #pragma unroll
            for (int i = 0; i < 2; i++)
                cpa16(bS + brow[i] * XA_STRIDE + bc[i] * 16, Bg + (size_t)brow[i] * Eq + k0 + bc[i] * 8);
            CP_COMMIT();
        }

        u32 oA = buf * XA_HALF, oB = buf * XB_HALF;
        #pragma unroll
        for (int s = 0; s < 4; s++) {
            u32 a[4], b0[4], b1[4], b2[4], b3[4];
            ldm4(a[0], a[1], a[2], a[3], aAddr + oA + s * 32);
            ldm4(b0[0], b0[1], b0[2], b0[3], bAddr + oB + s * 32);
            ldm4(b1[0], b1[1], b1[2], b1[3], bAddr + oB + s * 32 + 16);
            ldm4(b2[0], b2[1], b2[2], b2[3], bAddr + 4608 + oB + s * 32);
            ldm4(b3[0], b3[1], b3[2], b3[3], bAddr + 4608 + oB + s * 32 + 16);
            #pragma unroll
            for (int nt = 0; nt < 4; nt++) mma16816(acc[nt], a, b0[nt], b1[nt]);
            #pragma unroll
            for (int nt = 0; nt < 4; nt++) mma16816(acc[4 + nt], a, b2[nt], b3[nt]);
        }
    }

    int g = lane >> 2, tq = lane & 3;
    int bb = m0 >> 8;
    const float* tbr = g_tb + (size_t)bb * G4 + n0;
    #pragma unroll
    for (int rr = 0; rr < 2; rr++) {
        int m = m0 + wid * 16 + g + rr * 8;
        float* orow = g_xg + (size_t)m * G4 + n0;
        #pragma unroll
        for (int nt = 0; nt < 8; nt++) {
            int nn = nt * 8 + tq * 2;
            float2 tb2 = *(const float2*)(tbr + nn);
            float2 o;
            o.x = acc[nt][rr * 2 + 0] + tb2.x;
            o.y = acc[nt][rr * 2 + 1] + tb2.y;
            *(float2*)(orow + nn) = o;
        }
    }
}

// ---------------- persistent LSTM recurrence: bf16 P1 + fp8 cross ----------
// Smem layout (bytes):
//   A16 (bf16 h_hi chunk, 128 x 128B, stride 144):  0      + buf*18432  (2 bufs)
//   A8a (e4m3 h, 128 x 64B, stride 80):             36864  + buf*10240
//   A8l (e4m3 h_lo*512):                            57344  + buf*10240
//   B16 (bf16 w_hi persistent, 16 ch x 32 x 144B):  77824  + c*4608
//   B8LO (e4m3 w_lo*2^17, 32 x 1024B, stride 1040): 151552
//   B8HI (e4m3 w*2^8):                              184832
#define RA16   0
#define RA16B  18432
#define RA8A   36864
#define RA8L   57344
#define RA8B   10240
#define RB16   77824
#define RB8LO  151552
#define RB8HI  184832
#define RNN_SMEM 218112

__global__ __launch_bounds__(256) void k_rnn() {
    extern __shared__ char dsm[];
    int tid = threadIdx.x, wid = tid >> 5, lane = tid & 31;
    int n = blockIdx.x;
    u32 sb = smem_u32(dsm);
    int gid = lane >> 2, tig = lane & 3;

    // A16 cp mapping (4 x 16B per thread per chunk)
    int arow[4], ac[4];
    #pragma unroll
    for (int i = 0; i < 4; i++) { int u = tid + i * 256; arow[i] = u >> 3; ac[i] = u & 7; }
    // A8 cp mapping (2 x 16B per thread per buffer per chunk)
    int a8r[2], a8q[2];
    #pragma unroll
    for (int i = 0; i < 2; i++) { int u = tid + i * 256; a8r[i] = u >> 2; a8q[i] = u & 3; }

    // ---- persistent B loads ----
    {
        int brow = tid >> 3, bc = tid & 7;
        size_t grow = (size_t)((brow >> 3) * Hq + n * NH + (brow & 7)) * Hq;
        u32 d16 = sb + RB16 + brow * 144 + bc * 16;
        #pragma unroll
        for (int c = 0; c < 16; c++)
            cpa16(d16 + c * 4608, g_whi + grow + c * 64 + bc * 8);

        int r32 = tid >> 3, q0 = tid & 7;
        size_t grow8 = (size_t)((r32 >> 3) * Hq + n * NH + (r32 & 7)) * Hq;
        u32 dlo = sb + RB8LO + r32 * 1040;
        u32 dhi = sb + RB8HI + r32 * 1040;
        #pragma unroll
        for (int i = 0; i < 8; i++) {
            int q = q0 + 8 * i;
            cpa16(dlo + q * 16, g_w8lo + grow8 + q * 16);
            cpa16(dhi + q * 16, g_w8hi + grow8 + q * 16);
        }
        CP_COMMIT();
    }

    // ldmatrix addresses
    int amrow = wid * 16 + (lane & 7) + ((lane >> 3) & 1) * 8;
    u32 aAddr = sb + RA16 + amrow * 144 + (lane >> 4) * 16;
    u32 bAddr16 = sb + RB16 + lane * 144;
    // fp8 LDS addresses
    u32 a8base = (wid * 16 + gid) * 80 + tig * 4;      // + RA8A/RA8L + buf*RA8B + ks*32 (+640/+16/+656)
    u32 b8lo = sb + RB8LO + gid * 1040 + tig * 4;      // + nt*8320 + koff (+16)
    u32 b8hi = sb + RB8HI + gid * 1040 + tig * 4;

    int g = lane >> 2, tq = lane & 3;
    int u0 = tq * 2;
    float creg[4] = {0.f, 0.f, 0.f, 0.f};

    CP_WAIT0();
    __syncthreads();

    for (int t = 0; t < Tq; t++) {
        int ph = t & 1;
        const __nv_bfloat16* hh = g_hhi + (size_t)ph * BH;
        const u8* h8a = g_h8a + (size_t)ph * BH;
        const u8* h8l = g_h8lo + (size_t)ph * BH;

        float accP[4][4], accX[4][4];
        #pragma unroll
        for (int i = 0; i < 4; i++) {
            accP[i][0]=0.f; accP[i][1]=0.f; accP[i][2]=0.f; accP[i][3]=0.f;
            accX[i][0]=0.f; accX[i][1]=0.f; accX[i][2]=0.f; accX[i][3]=0.f;
        }

        // issue chunk 0 into buf 0
        {
            u32 d16 = sb + RA16;
            #pragma unroll
            for (int i = 0; i < 4; i++)
                cpa16(d16 + arow[i] * 144 + ac[i] * 16, hh + (size_t)arow[i] * Hq + ac[i] * 8);
            u32 d8a = sb + RA8A, d8l = sb + RA8L;
            #pragma unroll
            for (int i = 0; i < 2; i++) {
                size_t off = (size_t)a8r[i] * Hq + a8q[i] * 16;
                u32 so = a8r[i] * 80 + a8q[i] * 16;
                cpa16(d8a + so, h8a + off);
                cpa16(d8l + so, h8l + off);
            }
            CP_COMMIT();
        }

        for (int c = 0; c < 16; c++) {
            int buf = c & 1;
            CP_WAIT0();
            __syncthreads();
            if (c < 15) {
                int k0 = (c + 1) * 64;
                u32 d16 = sb + RA16 + (buf ^ 1) * RA16B;
                #pragma unroll
                for (int i = 0; i < 4; i++)
                    cpa16(d16 + arow[i] * 144 + ac[i] * 16, hh + (size_t)arow[i] * Hq + k0 + ac[i] * 8);
                u32 d8a = sb + RA8A + (buf ^ 1) * RA8B;
                u32 d8l = sb + RA8L + (buf ^ 1) * RA8B;
                #pragma unroll
                for (int i = 0; i < 2; i++) {
                    size_t off = (size_t)a8r[i] * Hq + k0 + a8q[i] * 16;
                    u32 so = a8r[i] * 80 + a8q[i] * 16;
                    cpa16(d8a + so, h8a + off);
                    cpa16(d8l + so, h8l + off);
                }
                CP_COMMIT();
            }

            // ---- P1: bf16 hi*hi ----
            u32 oA = buf * RA16B;
            u32 oB = c * 4608;
            #pragma unroll
            for (int s = 0; s < 4; s++) {
                u32 ah[4], bh0[4], bh1[4];
                ldm4(ah[0], ah[1], ah[2], ah[3], aAddr + oA + s * 32);
                ldm4(bh0[0], bh0[1], bh0[2], bh0[3], bAddr16 + oB + s * 32);
                ldm4(bh1[0], bh1[1], bh1[2], bh1[3], bAddr16 + oB + s * 32 + 16);
                #pragma unroll
                for (int nt = 0; nt < 4; nt++) mma16816(accP[nt], ah, bh0[nt], bh1[nt]);
            }

            // ---- cross: fp8 m16n8k32, shared scale 2^17 ----
            u32 oa8a = sb + RA8A + buf * RA8B + a8base;
            u32 oa8l = sb + RA8L + buf * RA8B + a8base;
            #pragma unroll
            for (int ks = 0; ks < 2; ks++) {
                u32 k32 = ks * 32;
                u32 aa[4], al[4];
                aa[0] = lds32(oa8a + k32);        aa[1] = lds32(oa8a + k32 + 640);
                aa[2] = lds32(oa8a + k32 + 16);   aa[3] = lds32(oa8a + k32 + 656);
                al[0] = lds32(oa8l + k32);        al[1] = lds32(oa8l + k32 + 640);
                al[2] = lds32(oa8l + k32 + 16);   al[3] = lds32(oa8l + k32 + 656);
                u32 koff = c * 64 + k32;
                #pragma unroll
                for (int nt = 0; nt < 4; nt++) {
                    u32 w0 = lds32(b8lo + nt * 8320 + koff);
                    u32 w1 = lds32(b8lo + nt * 8320 + koff + 16);
                    u32 v0 = lds32(b8hi + nt * 8320 + koff);
                    u32 v1 = lds32(b8hi + nt * 8320 + koff + 16);
                    mma16832q(accX[nt], aa, w0, w1);   // h * w_lo
                    mma16832q(accX[nt], al, v0, v1);   // h_lo * w
                }
            }
        }

        // ---- epilogue ----
        int phn = (t + 1) & 1;
        #pragma unroll
        for (int rr = 0; rr < 2; rr++) {
            int b = wid * 16 + g + rr * 8;
            const float* xr = g_xg + ((size_t)b * Tq + t) * G4 + n * NH + u0;
            float2 x0 = *(const float2*)(xr);
            float2 x1 = *(const float2*)(xr + Hq);
            float2 x2 = *(const float2*)(xr + 2 * Hq);
            float2 x3 = *(const float2*)(xr + 3 * Hq);

            float i0 = sigmoidf(accP[0][rr*2+0] + accX[0][rr*2+0] * CROSS_INV + x0.x);
            float f0 = sigmoidf(accP[1][rr*2+0] + accX[1][rr*2+0] * CROSS_INV + x1.x);
            float gg0 = tanhf(accP[2][rr*2+0] + accX[2][rr*2+0] * CROSS_INV + x2.x);
            float o0 = sigmoidf(accP[3][rr*2+0] + accX[3][rr*2+0] * CROSS_INV + x3.x);
            float i1 = sigmoidf(accP[0][rr*2+1] + accX[0][rr*2+1] * CROSS_INV + x0.y);
            float f1 = sigmoidf(accP[1][rr*2+1] + accX[1][rr*2+1] * CROSS_INV + x1.y);
            float gg1 = tanhf(accP[2][rr*2+1] + accX[2][rr*2+1] * CROSS_INV + x2.y);
            float o1 = sigmoidf(accP[3][rr*2+1] + accX[3][rr*2+1] * CROSS_INV + x3.y);

            float c0 = f0 * creg[rr*2+0] + i0 * gg0;
            float c1 = f1 * creg[rr*2+1] + i1 * gg1;
            creg[rr*2+0] = c0;
            creg[rr*2+1] = c1;
            float hx = o0 * tanhf(c0);
            float hy = o1 * tanhf(c1);

            size_t hob = (size_t)phn * BH + (size_t)b * Hq + n * NH + u0;
            __nv_bfloat162 hi2;
            hi2.x = __float2bfloat16(hx);
            hi2.y = __float2bfloat16(hy);
            __stcg((unsigned int*)(g_hhi + hob), *(unsigned int*)&hi2);

            __nv_fp8x2_storage_t pa = __nv_cvt_float2_to_fp8x2(make_float2(hx, hy),
                                        __NV_SATFINITE, __NV_E4M3);
            float lx = (hx - __bfloat162float(hi2.x)) * 512.0f;
            float ly = (hy - __bfloat162float(hi2.y)) * 512.0f;
            __nv_fp8x2_storage_t pl = __nv_cvt_float2_to_fp8x2(make_float2(lx, ly),
                                        __NV_SATFINITE, __NV_E4M3);
            __stcg((unsigned short*)(g_h8a + hob), (unsigned short)pa);
            __stcg((unsigned short*)(g_h8lo + hob), (unsigned short)pl);

            if (t == Tq - 1) {
                float2 hv; hv.x = hx; hv.y = hy;
                *(float2*)(g_hbuf + (size_t)b * Hq + n * NH + u0) = hv;
            }
        }

        // ---- global barrier between steps ----
        if (t < Tq - 1) {
            __threadfence();
            __syncthreads();
            if (tid == 0) {
                atomicAdd(&g_bar, 1u);
                unsigned int tgt = 128u * (t + 1);
                volatile unsigned int* p = &g_bar;
                while (*p < tgt) { }
                __threadfence();
            }
            __syncthreads();
        }
    }
}

// ---------------- fc1 ----------------
__global__ __launch_bounds__(256) void k_fc1(const float* __restrict__ fc1_w,
                                             const float* __restrict__ fc1_b) {
    int b = blockIdx.y;
    int f = blockIdx.x * 8 + (threadIdx.x >> 5);
    int lane = threadIdx.x & 31;
    const float* hr = g_hbuf + (size_t)b * Hq;
    const float* wr = fc1_w + (size_t)f * Hq;
    float s = 0.f;
    for (int k = lane; k < Hq; k += 32) s += hr[k] * wr[k];
    #pragma unroll
    for (int off = 16; off; off >>= 1) s += __shfl_xor_sync(0xffffffffu, s, off);
    if (lane == 0) g_h1[b * Fq + f] = s + fc1_b[f];
}

// ---------------- BN stats ----------------
__global__ void k_bn(const float* __restrict__ gamma, const float* __restrict__ beta) {
    int f = threadIdx.x;
    float s = 0.f, ss = 0.f;
    for (int b = 0; b < Bq; b++) { float v = g_h1[b * Fq + f]; s += v; ss += v * v; }
    float mu = s * (1.f / Bq);
    float var = ss * (1.f / Bq) - mu * mu;
    float rstd = rsqrtf(var + 1e-5f);
    float sc = rstd * gamma[f];
    g_s[f] = sc;
    g_t[f] = beta[f] - mu * sc;
}

// ---------------- fc2 ----------------
__global__ __launch_bounds__(320) void k_out(const float* __restrict__ fc2_w,
                                             const float* __restrict__ fc2_b,
                                             float* __restrict__ out) {
    int b = blockIdx.x;
    int o = threadIdx.x >> 5;
    int lane = threadIdx.x & 31;
    const float* h1r = g_h1 + (size_t)b * Fq;
    const float* wr = fc2_w + (size_t)o * Fq;
    float s = 0.f;
    for (int f = lane; f < Fq; f += 32) s += (h1r[f] * g_s[f] + g_t[f]) * wr[f];
    #pragma unroll
    for (int off = 16; off; off >>= 1) s += __shfl_xor_sync(0xffffffffu, s, off);
    if (lane == 0) out[b * Oq + o] = s + fc2_b[o];
}

// ---------------- launch ----------------
extern "C" void kernel_launch(void* const* d_in, const int* in_sizes, int n_in,
                              void* d_out, int out_size) {
    const int*   x     = (const int*)  d_in[0];
    const float* x_top = (const float*)d_in[1];
    const float* emb   = (const float*)d_in[2];
    const float* w_ih  = (const float*)d_in[3];
    const float* w_hh  = (const float*)d_in[4];
    const float* w_th  = (const float*)d_in[5];
    const float* bias  = (const float*)d_in[6];
    const float* fc1_w = (const float*)d_in[7];
    const float* fc1_b = (const float*)d_in[8];
    const float* gamma = (const float*)d_in[9];
    const float* beta  = (const float*)d_in[10];
    const float* fc2_w = (const float*)d_in[11];
    const float* fc2_b = (const float*)d_in[12];
    float* out = (float*)d_out;

    cudaFuncSetAttribute(k_xg_t, cudaFuncAttributeMaxDynamicSharedMemorySize, XG_SMEM);
    cudaFuncSetAttribute(k_rnn,  cudaFuncAttributeMaxDynamicSharedMemorySize, RNN_SMEM);

    k_init<<<(BH + 255) / 256, 256>>>();
    k_wsplit<<<(G4 * Hq / 4) / 256, 256>>>(w_hh);
    k_wihb<<<(G4 * Eq / 4) / 256, 256>>>(w_ih);
    k_xeb<<<(Bq * Tq * Eq / 4) / 256, 256>>>(x, emb);
    k_topic<<<Bq, 256>>>(x_top, w_th, bias);
    dim3 gxg(G4 / 64, (Bq * Tq) / 128);
    k_xg_t<<<gxg, 256, XG_SMEM>>>();
    k_rnn<<<128, 256, RNN_SMEM>>>();
    k_fc1<<<dim3(Fq / 8, Bq), 256>>>(fc1_w, fc1_b);
    k_bn<<<1, Fq>>>(gamma, beta);
    k_out<<<Bq, 320>>>(fc2_w, fc2_b, out);
}